// round 2
// baseline (speedup 1.0000x reference)
#include <cuda_runtime.h>

#define HH 4
#define BB 1024
#define LL 200
#define DQv 512
#define DFv 128
#define DD1 128
#define DD2 64

// Collapsed weights + precomputed fq (static device scratch — allowed)
__device__ float g_Wq[HH * DQv * DD2];   // [h][k][c]
__device__ float g_bq[HH * DD2];
__device__ float g_Wc[HH * DFv * 128];   // [h][k][c]  c<64: f-path, c>=64: v-path
__device__ float g_bc[HH * 128];
__device__ float g_fq[BB * HH * DD2];    // [b][h][c] silu(query@Wq_eff+bq_eff)

// ---------------- packed f32x2 helpers ----------------
__device__ __forceinline__ void ffma2(unsigned long long& d, unsigned long long a, unsigned long long b) {
    asm("fma.rn.f32x2 %0, %1, %2, %0;" : "+l"(d) : "l"(a), "l"(b));
}
__device__ __forceinline__ float2 unpk(unsigned long long v) {
    unsigned int lo, hi;
    asm("mov.b64 {%0, %1}, %2;" : "=r"(lo), "=r"(hi) : "l"(v));
    return make_float2(__uint_as_float(lo), __uint_as_float(hi));
}
__device__ __forceinline__ float silu_f(float x) {
    return x / (1.f + __expf(-x));
}

// ---------------- weight collapse kernels ----------------
__global__ void collapse_q_kernel(const float* __restrict__ Wq1, const float* __restrict__ bq1,
                                  const float* __restrict__ Wq2, const float* __restrict__ bq2) {
    int idx = blockIdx.x * 256 + threadIdx.x;      // < 4*512*64 = 131072
    int c = idx & 63;
    int k = (idx >> 6) & 511;
    int h = idx >> 15;
    const float* a  = Wq1 + (h * DQv + k) * DD1;
    const float* w2 = Wq2 + h * DD1 * DD2 + c;
    float acc = 0.f;
#pragma unroll 8
    for (int j = 0; j < DD1; ++j) acc += a[j] * w2[j * DD2];
    g_Wq[idx] = acc;
    if (k == 0) {
        float bb = bq2[h * DD2 + c];
        const float* b1p = bq1 + h * DD1;
#pragma unroll 8
        for (int j = 0; j < DD1; ++j) bb += b1p[j] * w2[j * DD2];
        g_bq[h * DD2 + c] = bb;
    }
}

__global__ void collapse_fv_kernel(const float* __restrict__ Wf1, const float* __restrict__ bf1,
                                   const float* __restrict__ Wf2, const float* __restrict__ bf2,
                                   const float* __restrict__ Wv1, const float* __restrict__ bv1,
                                   const float* __restrict__ Wv2, const float* __restrict__ bv2) {
    int idx = blockIdx.x * 256 + threadIdx.x;      // < 4*128*128 = 65536
    int c = idx & 127;
    int k = (idx >> 7) & 127;
    int h = idx >> 14;
    const float *W1, *W2, *B1, *B2;
    int cc;
    if (c < 64) { W1 = Wf1; W2 = Wf2; B1 = bf1; B2 = bf2; cc = c; }
    else        { W1 = Wv1; W2 = Wv2; B1 = bv1; B2 = bv2; cc = c - 64; }
    const float* a  = W1 + (h * DFv + k) * DD1;
    const float* w2 = W2 + h * DD1 * DD2 + cc;
    float acc = 0.f;
#pragma unroll 8
    for (int j = 0; j < DD1; ++j) acc += a[j] * w2[j * DD2];
    g_Wc[idx] = acc;
    if (k == 0) {
        float bb = B2[h * DD2 + cc];
        const float* b1p = B1 + h * DD1;
#pragma unroll 8
        for (int j = 0; j < DD1; ++j) bb += b1p[j] * w2[j * DD2];
        g_bc[h * 128 + c] = bb;
    }
}

// ---------------- fq kernel: g_fq = silu(query @ Wq_eff + bq_eff) ----------------
// grid = 32 b-groups (32 b each) x 4 heads = 128 blocks, 256 threads.
__global__ __launch_bounds__(256) void fq_kernel(const float* __restrict__ query) {
    __shared__ float qs[32 * 68];     // padded stride 68 to dodge bank conflicts
    __shared__ float ws[64 * 64];
    const int tid = threadIdx.x;
    const int h  = blockIdx.x & 3;
    const int bg = blockIdx.x >> 2;
    const int bl = tid >> 3;          // 0..31  local b
    const int cg = tid & 7;           // 0..7   column-octet

    float acc[8];
#pragma unroll
    for (int j = 0; j < 8; ++j) acc[j] = 0.f;

    for (int kc = 0; kc < 8; ++kc) {
        __syncthreads();
        // stage query chunk [32 b][64 k]
#pragma unroll
        for (int it = 0; it < 8; ++it) {
            int idx = tid + it * 256;             // < 2048
            int bb = idx >> 6, kk = idx & 63;
            qs[bb * 68 + kk] = query[(bg * 32 + bb) * DQv + kc * 64 + kk];
        }
        // stage W chunk [64 k][64 c]
#pragma unroll
        for (int it = 0; it < 16; ++it) {
            int idx = tid + it * 256;             // < 4096
            int kk = idx >> 6, cc = idx & 63;
            ws[kk * 64 + cc] = g_Wq[(h * DQv + kc * 64 + kk) * DD2 + cc];
        }
        __syncthreads();
#pragma unroll 4
        for (int k = 0; k < 64; ++k) {
            float qv = qs[bl * 68 + k];
            float4 w01 = *reinterpret_cast<const float4*>(ws + k * 64 + cg * 8);
            float4 w23 = *reinterpret_cast<const float4*>(ws + k * 64 + cg * 8 + 4);
            acc[0] += qv * w01.x; acc[1] += qv * w01.y;
            acc[2] += qv * w01.z; acc[3] += qv * w01.w;
            acc[4] += qv * w23.x; acc[5] += qv * w23.y;
            acc[6] += qv * w23.z; acc[7] += qv * w23.w;
        }
    }
    int bglob = bg * 32 + bl;
#pragma unroll
    for (int j = 0; j < 8; ++j) {
        int c = cg * 8 + j;
        float z = acc[j] + g_bq[h * DD2 + c];
        g_fq[bglob * 256 + h * 64 + c] = silu_f(z);
    }
}

// ---------------- fused main kernel: one block per (b,h) ----------------
// smem (floats): W 16384 | factd 20480 (80 rows x 256 dup) | fv 12800 | logits 208 | fq 64 | bc 128 | red 256 | misc 32
#define SMEM_FLOATS (16384 + 20480 + 12800 + 208 + 64 + 128 + 256 + 32)
#define SMEM_BYTES  (SMEM_FLOATS * 4)

template<int R>
__device__ __forceinline__ void tile_work(
    const float* __restrict__ W_s, const float* __restrict__ factd,
    float* __restrict__ fv_s, float* __restrict__ logits_s,
    float4 fq4, float4 bc4,
    int tb, int rg, int c4,
    const int* __restrict__ mask, const float* __restrict__ mm,
    int b, float t1a, float t1b, float cb1, float cb2, float cb3)
{
    const int lbase = rg * R;
    unsigned long long acc0[R], acc1[R];
#pragma unroll
    for (int i = 0; i < R; ++i) { acc0[i] = 0ull; acc1[i] = 0ull; }

#pragma unroll 2
    for (int k4 = 0; k4 < 32; ++k4) {
        ulonglong2 w0 = *reinterpret_cast<const ulonglong2*>(W_s + (k4 * 4 + 0) * 128 + c4 * 4);
        ulonglong2 w1 = *reinterpret_cast<const ulonglong2*>(W_s + (k4 * 4 + 1) * 128 + c4 * 4);
        ulonglong2 w2 = *reinterpret_cast<const ulonglong2*>(W_s + (k4 * 4 + 2) * 128 + c4 * 4);
        ulonglong2 w3 = *reinterpret_cast<const ulonglong2*>(W_s + (k4 * 4 + 3) * 128 + c4 * 4);
#pragma unroll
        for (int i = 0; i < R; ++i) {
            const float* fp = factd + (lbase + i) * 256 + k4 * 8;
            ulonglong2 fa = *reinterpret_cast<const ulonglong2*>(fp);      // {f0,f0},{f1,f1}
            ulonglong2 fb = *reinterpret_cast<const ulonglong2*>(fp + 4);  // {f2,f2},{f3,f3}
            ffma2(acc0[i], fa.x, w0.x); ffma2(acc1[i], fa.x, w0.y);
            ffma2(acc0[i], fa.y, w1.x); ffma2(acc1[i], fa.y, w1.y);
            ffma2(acc0[i], fb.x, w2.x); ffma2(acc1[i], fb.x, w2.y);
            ffma2(acc0[i], fb.y, w3.x); ffma2(acc1[i], fb.y, w3.y);
        }
    }

    // epilogue: bias + silu; f-lanes (c4<16) form dot partials, v-lanes stash fv
    float pdot[R];
#pragma unroll
    for (int i = 0; i < R; ++i) {
        float2 a0 = unpk(acc0[i]);
        float2 a1 = unpk(acc1[i]);
        float s0 = silu_f(a0.x + bc4.x);
        float s1 = silu_f(a0.y + bc4.y);
        float s2 = silu_f(a1.x + bc4.z);
        float s3 = silu_f(a1.y + bc4.w);
        if (c4 < 16) {
            pdot[i] = s0 * fq4.x + s1 * fq4.y + s2 * fq4.z + s3 * fq4.w;
        } else {
            float4 vv = make_float4(s0, s1, s2, s3);
            *reinterpret_cast<float4*>(fv_s + (tb + lbase + i) * 64 + (c4 - 16) * 4) = vv;
            pdot[i] = 0.f;
        }
    }
    if (c4 < 16) {
#pragma unroll
        for (int i = 0; i < R; ++i) {
#pragma unroll
            for (int off = 8; off > 0; off >>= 1)
                pdot[i] += __shfl_xor_sync(0x0000ffffu, pdot[i], off);
        }
        if (c4 < R) {
            float d0 = pdot[0];
#pragma unroll
            for (int i = 1; i < R; ++i)
                if (c4 == i) d0 = pdot[i];
            int l = tb + lbase + c4;
            float mk = (float)mask[b * 200 + l];
            float dd = d0 + (-1e9f) * (1.f - mk);       // mask BEFORE cosine mixing (matches ref)
            float bias = mm[b * 200 + l] / t1a + mm[204800 + b * 200 + l] / t1b;
            logits_s[l] = cb1 * dd + cb2 * bias + cb3 * dd * bias;
        }
    }
}

__global__ __launch_bounds__(256, 1) void mha_main_kernel(
    const float* __restrict__ fact,
    const int* __restrict__ mask, const float* __restrict__ mm,
    const float* __restrict__ tau1, const float* __restrict__ tau2,
    float* __restrict__ out)
{
    extern __shared__ float sm[];
    float* W_s      = sm;                 // [128][128]
    float* factd    = W_s + 16384;        // [80][256]  duplicated pairs
    float* fv_s     = factd + 20480;      // [200][64]
    float* logits_s = fv_s + 12800;       // [200] (+pad)
    float* fq_s     = logits_s + 208;     // [64]
    float* bc_s     = fq_s + 64;          // [128]
    float* red_s    = bc_s + 128;         // [256]
    float* misc     = red_s + 256;        // [32]

    const int tid = threadIdx.x;
    const int b = blockIdx.x >> 2;
    const int h = blockIdx.x & 3;
    const int rg = tid >> 5;              // warp id
    const int c4 = tid & 31;              // column quad

    // stage combined weights into smem
    {
        const float4* gw = reinterpret_cast<const float4*>(g_Wc + h * 16384);
        float4* ws4 = reinterpret_cast<float4*>(W_s);
#pragma unroll
        for (int i = 0; i < 16; ++i) ws4[tid + 256 * i] = gw[tid + 256 * i];
    }
    if (tid < 128) bc_s[tid] = g_bc[h * 128 + tid];
    if (tid < 64)  fq_s[tid] = g_fq[b * 256 + h * 64 + tid];
    __syncthreads();

    const float t1a = tau1[h], t1b = tau1[4 + h];
    const float cb1 = tau2[h], cb2 = tau2[4 + h], cb3 = tau2[8 + h];

    float4 bc4 = *reinterpret_cast<const float4*>(bc_s + c4 * 4);
    float4 fq4 = make_float4(0.f, 0.f, 0.f, 0.f);
    if (c4 < 16) fq4 = *reinterpret_cast<const float4*>(fq_s + c4 * 4);

    const float4* fact4 = reinterpret_cast<const float4*>(fact + (long)b * 200 * 128);

    // ---- 3 tiles: 80 + 80 + 40 rows ----
#pragma unroll 1
    for (int t = 0; t < 3; ++t) {
        const int tb  = (t == 0) ? 0 : (t == 1 ? 80 : 160);
        const int R_T = (t == 2) ? 40 : 80;
        __syncthreads();    // protect factd rewrite against previous tile reads
        for (int idx = tid; idx < R_T * 32; idx += 256) {
            int row = idx >> 5, q = idx & 31;
            float4 f = fact4[(tb + row) * 32 + q];
            float* dst = factd + row * 256 + q * 8;
            *reinterpret_cast<float4*>(dst)     = make_float4(f.x, f.x, f.y, f.y);
            *reinterpret_cast<float4*>(dst + 4) = make_float4(f.z, f.z, f.w, f.w);
        }
        __syncthreads();
        if (R_T == 80)
            tile_work<10>(W_s, factd, fv_s, logits_s, fq4, bc4, tb, rg, c4,
                          mask, mm, b, t1a, t1b, cb1, cb2, cb3);
        else
            tile_work<5>(W_s, factd, fv_s, logits_s, fq4, bc4, tb, rg, c4,
                         mask, mm, b, t1a, t1b, cb1, cb2, cb3);
    }
    __syncthreads();

    // ---- softmax over L=200 ----
    float v = (tid < 200) ? logits_s[tid] : -3.0e38f;
    float mxv = v;
#pragma unroll
    for (int off = 16; off > 0; off >>= 1)
        mxv = fmaxf(mxv, __shfl_xor_sync(0xffffffffu, mxv, off));
    if (c4 == 0) misc[rg] = mxv;
    __syncthreads();
    if (tid == 0) {
        float m = misc[0];
#pragma unroll
        for (int i = 1; i < 8; ++i) m = fmaxf(m, misc[i]);
        misc[8] = m;
    }
    __syncthreads();
    const float MX = misc[8];
    float e = (tid < 200) ? expf(v - MX) : 0.f;
    float se = e;
#pragma unroll
    for (int off = 16; off > 0; off >>= 1)
        se += __shfl_xor_sync(0xffffffffu, se, off);
    if (c4 == 0) misc[16 + rg] = se;
    __syncthreads();
    if (tid == 0) {
        float s = 0.f;
#pragma unroll
        for (int i = 0; i < 8; ++i) s += misc[16 + i];
        misc[9] = 1.f / s;
    }
    __syncthreads();
    const float invS = misc[9];
    if (tid < 200) logits_s[tid] = e * invS + 1e-7f;   // alphas + 1e-7
    __syncthreads();

    // ---- out[c] = sum_l fv[l][c] * w[l] ----
    {
        int c = tid & 63, lg = tid >> 6;
        float o = 0.f;
        for (int l = lg; l < 200; l += 4)
            o += fv_s[l * 64 + c] * logits_s[l];
        red_s[tid] = o;
    }
    __syncthreads();
    if (tid < 64) {
        float r = red_s[tid] + red_s[64 + tid] + red_s[128 + tid] + red_s[192 + tid];
        out[b * 256 + h * 64 + tid] = r;
    }
}

extern "C" void kernel_launch(void* const* d_in, const int* in_sizes, int n_in,
                              void* d_out, int out_size) {
    const float* query = (const float*)d_in[0];
    const float* fact  = (const float*)d_in[1];
    const int*   mask  = (const int*)  d_in[2];
    const float* mm    = (const float*)d_in[3];
    const float* Wq1   = (const float*)d_in[4];
    const float* bq1   = (const float*)d_in[5];
    const float* Wq2   = (const float*)d_in[6];
    const float* bq2   = (const float*)d_in[7];
    const float* Wf1   = (const float*)d_in[8];
    const float* bf1   = (const float*)d_in[9];
    const float* Wf2   = (const float*)d_in[10];
    const float* bf2   = (const float*)d_in[11];
    const float* Wv1   = (const float*)d_in[12];
    const float* bv1   = (const float*)d_in[13];
    const float* Wv2   = (const float*)d_in[14];
    const float* bv2   = (const float*)d_in[15];
    const float* tau1  = (const float*)d_in[16];
    const float* tau2  = (const float*)d_in[17];
    float* out = (float*)d_out;

    cudaFuncSetAttribute(mha_main_kernel, cudaFuncAttributeMaxDynamicSharedMemorySize, SMEM_BYTES);

    collapse_q_kernel<<<512, 256>>>(Wq1, bq1, Wq2, bq2);
    collapse_fv_kernel<<<256, 256>>>(Wf1, bf1, Wf2, bf2, Wv1, bv1, Wv2, bv2);
    fq_kernel<<<128, 256>>>(query);
    mha_main_kernel<<<BB * HH, 256, SMEM_BYTES>>>(fact, mask, mm, tau1, tau2, out);
}